// round 10
// baseline (speedup 1.0000x reference)
#include <cuda_runtime.h>

#define NN 64
#define MM 1728
#define THREADS_E 384
#define WARPS_PER_BLOCK 12
#define GRID_EMBED 148
#define FS 4          // fit blocks per atom

// ---------------- device scratch (no allocations allowed) ----------------
// Self-cleaning protocol: g_d, g_sync, g_done, g_thead, g_ntiles, g_prep_done
// are zero at the start of every kernel_launch call (static zero-init on the
// first call; k_fit's final block restores them at the end of each call).
__device__ float g_d[NN * 384];
__device__ float g_h1[NN * 256];
__device__ float g_h2[NN * 256];
__device__ float g_h3[NN * 128];
__device__ float g_pre[NN * 3];
__device__ unsigned g_sync[3 * NN];
__device__ int g_done = 0;
__device__ short g_plist[128][896];   // per-(n,parity) compacted m lists
__device__ int g_tlist[3456];         // flat tile queue entries
__device__ int g_ntiles = 0;
__device__ int g_thead = 0;
__device__ unsigned g_prep_done = 0;

__device__ __forceinline__ float lrelu(float v) { return v > 0.f ? v : 0.01f * v; }

// -------- packed f32x2 helpers --------
__device__ __forceinline__ unsigned long long pack2(float v) {
    unsigned long long r;
    asm("mov.b64 %0, {%1, %1};" : "=l"(r) : "r"(__float_as_uint(v)));
    return r;
}
__device__ __forceinline__ void ffma2(unsigned long long& acc, unsigned long long a,
                                      unsigned long long b) {
    asm("fma.rn.f32x2 %0, %1, %2, %0;" : "+l"(acc) : "l"(a), "l"(b));
}
__device__ __forceinline__ void unpack2(unsigned long long v, float& a, float& b) {
    unsigned int lo, hi;
    asm("mov.b64 {%0, %1}, %2;" : "=r"(lo), "=r"(hi) : "l"(v));
    a = __uint_as_float(lo);
    b = __uint_as_float(hi);
}
__device__ __forceinline__ void l2_prefetch(const float* p) {
    asm volatile("prefetch.global.L2 [%0];" :: "l"(p));
}
__device__ __forceinline__ unsigned ld_acq(const unsigned* p) {
    unsigned v;
    asm volatile("ld.acquire.gpu.u32 %0, [%1];" : "=r"(v) : "l"(p) : "memory");
    return v;
}
__device__ __forceinline__ void spin_wait(const unsigned* p, unsigned target) {
    if (ld_acq(p) >= target) return;
    while (ld_acq(p) < target) __nanosleep(64);
}

// ---------------- kernel 1: persistent embedding (fused prep + MLP + contraction) --
// keep[n][m] = (dist <= 25) && !(c==0 && j==n); list (n,p) holds kept m with
// j parity p (keeps pid warp-uniform downstream). Rank-collapse proof: for c=0
// every pair has dist = |x[j]-x[n]| <= sqrt(300) < 25 (x in [0,10]^3), so the
// first 64 entries of each row are all masked; the (n+1)-th masked entry
// (rank==n) is exactly m = n, the self-pair.
//
// smem layout (floats)
#define SW_W1 0
#define SW_B1 288
#define SW_W2 384
#define SW_B2 6528
#define SW_W3 6720
#define SW_B3 31296
#define SW_TOTAL 31680
#define RELK_OFF SW_TOTAL                       // 12 warps * 32 * 4 = 1536
#define SG_OFF (RELK_OFF + 1536)                // 12 warps * 32 * 36 = 13824
#define SMEM_FLOATS (SG_OFF + 13824)            // 47040 floats = 188160 B

__global__ void __launch_bounds__(THREADS_E, 1)
k_embed(const float* __restrict__ x, const int* __restrict__ at,
        const float* __restrict__ We1, const float* __restrict__ be1,
        const float* __restrict__ We2, const float* __restrict__ be2,
        const float* __restrict__ We3, const float* __restrict__ be3,
        const float* __restrict__ Wl1, const float* __restrict__ Wl2,
        const float* __restrict__ Wl3) {
    extern __shared__ float sm[];
    __shared__ float sx[192];
    __shared__ int sat[64];
    int tid = threadIdx.x;
    int warp = tid >> 5, lane = tid & 31;

    if (tid < 192) sx[tid] = x[tid];
    if (tid >= 192 && tid < 256) sat[tid - 192] = at[tid - 192];
    __syncthreads();

    // ---- fused prep: blocks 0..127, warp 0 each build one compacted list ----
    if (blockIdx.x < 128 && warp == 0) {
        int L = blockIdx.x;
        int n = L >> 1, p = L & 1;
        float xn0 = sx[n * 3 + 0], xn1 = sx[n * 3 + 1], xn2 = sx[n * 3 + 2];
        int cnt = 0;
        for (int tb = 0; tb < 864; tb += 32) {
            int t = tb + lane;
            int c3 = t >> 5, jj = t & 31;
            int j = 2 * jj + p;
            int a = c3 / 9, b = (c3 / 3) % 3, dd = c3 % 3;
            float r0 = sx[j * 3 + 0] + 10.f * a - xn0;
            float r1 = sx[j * 3 + 1] + 10.f * b - xn1;
            float r2 = sx[j * 3 + 2] + 10.f * dd - xn2;
            float d2 = r0 * r0 + r1 * r1 + r2 * r2;
            bool kb = (d2 <= 625.0f) && !(c3 == 0 && j == n);
            unsigned msk = __ballot_sync(0xffffffffu, kb);
            if (kb)
                g_plist[L][cnt + __popc(msk & ((1u << lane) - 1u))] =
                    (short)(c3 * 64 + j);
            cnt += __popc(msk);
        }
        if (lane == 0) {
            int nt = (cnt + 31) >> 5;
            int base = atomicAdd(&g_ntiles, nt);
            for (int i = 0; i < nt; i++) {
                int rem = min(cnt - i * 32, 32);
                g_tlist[base + i] = (L << 10) | (i << 5) | (rem - 1);
            }
            __threadfence();
            atomicAdd(&g_prep_done, 1u);
        }
    }

    // ---- stage all embedding weights into shared (warps 1..11 everywhere;
    //      warp 0 of non-prep blocks joins too) ----
    {
        int stid, sstr;
        if (blockIdx.x < 128) { stid = tid - 32; sstr = THREADS_E - 32; }
        else                  { stid = tid;      sstr = THREADS_E; }
        if (stid >= 0) {
            const float4* s4;
            float4* d4;
            s4 = (const float4*)We1; d4 = (float4*)(sm + SW_W1);
            for (int i = stid; i < 288 / 4; i += sstr) d4[i] = s4[i];
            s4 = (const float4*)be1; d4 = (float4*)(sm + SW_B1);
            for (int i = stid; i < 96 / 4; i += sstr) d4[i] = s4[i];
            s4 = (const float4*)We2; d4 = (float4*)(sm + SW_W2);
            for (int i = stid; i < 6144 / 4; i += sstr) d4[i] = s4[i];
            s4 = (const float4*)be2; d4 = (float4*)(sm + SW_B2);
            for (int i = stid; i < 192 / 4; i += sstr) d4[i] = s4[i];
            s4 = (const float4*)We3; d4 = (float4*)(sm + SW_W3);
            for (int i = stid; i < 24576 / 4; i += sstr) d4[i] = s4[i];
            s4 = (const float4*)be3; d4 = (float4*)(sm + SW_B3);
            for (int i = stid; i < 384 / 4; i += sstr) d4[i] = s4[i];

            // L2-prefetch fit-net weights (consumed by k_fit); no writeback.
            long long gtid = (long long)blockIdx.x * THREADS_E + stid;
            long long stride = (long long)GRID_EMBED * sstr;
            for (long long o = gtid * 32; o < 6291456LL; o += stride * 32)
                l2_prefetch(Wl1 + o);
            for (long long o = gtid * 32; o < 4194304LL; o += stride * 32)
                l2_prefetch(Wl2 + o);
            for (long long o = gtid * 32; o < 2097152LL; o += stride * 32)
                l2_prefetch(Wl3 + o);
        }
    }

    // wait for all 128 lists (all 148 blocks are co-resident: grid == #SM,
    // 1 block/SM -> spin is deadlock-free)
    spin_wait(&g_prep_done, 128u);
    __syncthreads();
    int ntot = g_ntiles;

    float* relkW = sm + RELK_OFF + warp * 128;   // 32 lanes * float4
    float* sgW = sm + SG_OFF + warp * 1152;      // 32 rows * 36
    float* myrow = sgW + lane * 36;

    for (;;) {
        int idx;
        if (lane == 0) idx = atomicAdd(&g_thead, 1);
        idx = __shfl_sync(0xffffffffu, idx, 0);
        if (idx >= ntot) break;
        int e = g_tlist[idx];
        int L = e >> 10;
        int chunk = (e >> 5) & 31;
        int rem = (e & 31) + 1;
        int n = L >> 1;
        bool valid = lane < rem;
        int m = valid ? (int)g_plist[L][(chunk << 5) + lane] : n;  // dummy: keep=0
        int c3 = m >> 6, j = m & 63;
        int a = c3 / 9, b = (c3 / 3) % 3, dd = c3 % 3;
        // rel = x[j] - x[n] + 10*(a,b,d)
        float r0 = sx[j * 3 + 0] + 10.f * a - sx[n * 3 + 0];
        float r1 = sx[j * 3 + 1] + 10.f * b - sx[n * 3 + 1];
        float r2 = sx[j * 3 + 2] + 10.f * dd - sx[n * 3 + 2];
        float keep = valid ? 1.f : 0.f;

        int tn = sat[n], tj = sat[j];
        int lo = min(tn, tj), hi = max(tn, tj);
        int pid = lo * 2 - (lo * (lo - 1)) / 2 + (hi - lo);

        ((float4*)relkW)[lane] = make_float4(r0 * keep, r1 * keep, r2 * keep, 0.f);

        // ---- layer 1: 3 -> 32 (scalar, tiny) ----
        float h1[32];
        {
            const float* W1 = sm + SW_W1 + pid * 96;
            const float4* B1 = (const float4*)(sm + SW_B1 + pid * 32);
            #pragma unroll
            for (int o4 = 0; o4 < 8; o4++) {
                float4 acc = B1[o4];
                float4 w0 = ((const float4*)(W1 + 0 * 32))[o4];
                float4 w1 = ((const float4*)(W1 + 1 * 32))[o4];
                float4 w2 = ((const float4*)(W1 + 2 * 32))[o4];
                acc.x += r0 * w0.x + r1 * w1.x + r2 * w2.x;
                acc.y += r0 * w0.y + r1 * w1.y + r2 * w2.y;
                acc.z += r0 * w0.z + r1 * w1.z + r2 * w2.z;
                acc.w += r0 * w0.w + r1 * w1.w + r2 * w2.w;
                h1[o4 * 4 + 0] = lrelu(acc.x);
                h1[o4 * 4 + 1] = lrelu(acc.y);
                h1[o4 * 4 + 2] = lrelu(acc.z);
                h1[o4 * 4 + 3] = lrelu(acc.w);
            }
        }

        // ---- layer 2: 32 -> 64, packed f32x2, two 32-output halves ----
        // (halving live accumulators: peak regs ~135 -> no spills at 384 thr)
        float h2[64];
        const ulonglong2* W2v = (const ulonglong2*)(sm + SW_W2 + pid * 2048);
        const ulonglong2* B2v = (const ulonglong2*)(sm + SW_B2 + pid * 64);
        #pragma unroll 1
        for (int half = 0; half < 2; half++) {
            unsigned long long acc2[16];
            #pragma unroll
            for (int o4 = 0; o4 < 8; o4++) {
                ulonglong2 bb = B2v[half * 8 + o4];
                acc2[2 * o4] = bb.x;
                acc2[2 * o4 + 1] = bb.y;
            }
            #pragma unroll
            for (int i = 0; i < 32; i++) {
                unsigned long long hp = pack2(h1[i]);
                const ulonglong2* wrow = W2v + i * 16 + half * 8;
                #pragma unroll
                for (int o4 = 0; o4 < 8; o4++) {
                    ulonglong2 w = wrow[o4];
                    ffma2(acc2[2 * o4], hp, w.x);
                    ffma2(acc2[2 * o4 + 1], hp, w.y);
                }
            }
            #pragma unroll
            for (int p = 0; p < 16; p++) {
                float va, vb;
                unpack2(acc2[p], va, vb);
                h2[half * 32 + 2 * p] = lrelu(va);
                h2[half * 32 + 2 * p + 1] = lrelu(vb);
            }
        }

        // ---- layer 3: 64 -> 128 in 4 chunks of 32, packed, fused contraction ----
        const ulonglong2* W3v = (const ulonglong2*)(sm + SW_W3 + pid * 8192);
        const ulonglong2* B3v = (const ulonglong2*)(sm + SW_B3 + pid * 128);
        #pragma unroll 1
        for (int k = 0; k < 4; k++) {
            unsigned long long acc3[16];
            #pragma unroll
            for (int o4 = 0; o4 < 8; o4++) {
                ulonglong2 bb = B3v[k * 8 + o4];
                acc3[2 * o4] = bb.x;
                acc3[2 * o4 + 1] = bb.y;
            }
            #pragma unroll
            for (int i = 0; i < 64; i++) {
                unsigned long long hp = pack2(h2[i]);
                const ulonglong2* wrow = W3v + i * 32 + k * 8;
                #pragma unroll
                for (int o4 = 0; o4 < 8; o4++) {
                    ulonglong2 w = wrow[o4];
                    ffma2(acc3[2 * o4], hp, w.x);
                    ffma2(acc3[2 * o4 + 1], hp, w.y);
                }
            }
            #pragma unroll
            for (int o4 = 0; o4 < 8; o4++) {
                float a0, a1, a2, a3;
                unpack2(acc3[2 * o4], a0, a1);
                unpack2(acc3[2 * o4 + 1], a2, a3);
                ((float4*)myrow)[o4] =
                    make_float4(lrelu(a0), lrelu(a1), lrelu(a2), lrelu(a3));
            }
            __syncwarp();
            // warp-local transpose reduce: lane owns output o = k*32 + lane
            float d0 = 0.f, d1 = 0.f, d2s = 0.f;
            #pragma unroll 8
            for (int q = 0; q < 32; q++) {
                float gv = sgW[q * 36 + lane];
                float4 rk = ((const float4*)relkW)[q];
                d0 += gv * rk.x;
                d1 += gv * rk.y;
                d2s += gv * rk.z;
            }
            __syncwarp();
            int o = k * 32 + lane;
            atomicAdd(&g_d[n * 384 + o * 3 + 0], d0);
            atomicAdd(&g_d[n * 384 + o * 3 + 1], d1);
            atomicAdd(&g_d[n * 384 + o * 3 + 2], d2s);
        }
        __syncwarp();
    }
}

// ---------------- kernel 2: multi-block per-atom fit network ----------------
// 4 blocks per atom; per-layer cross-block sync via release/acquire counters.
// All 256 blocks are co-resident (2 blocks/SM guaranteed) -> spins are safe.
__global__ void __launch_bounds__(256, 2)
k_fit(const float* __restrict__ Wl1, const float* __restrict__ bl1,
      const float* __restrict__ Wl2, const float* __restrict__ bl2,
      const float* __restrict__ Wl3, const float* __restrict__ bl3,
      const float* __restrict__ Wl4, const float* __restrict__ bl4,
      float* __restrict__ out) {
    __shared__ float sin[384];
    __shared__ float sp[256];
    int blk = blockIdx.x;
    int n = blk >> 2, s = blk & 3;
    int tid = threadIdx.x;

    for (int i = tid; i < 384; i += 256) sin[i] = g_d[n * 384 + i];
    __syncthreads();

    // ---- L1: 384 -> 256, this block owns outputs [s*64, s*64+64) ----
    {
        int ol = tid & 63;
        int p = tid >> 6;                       // 4 parts x 96 inputs
        const float* W = Wl1 + (size_t)n * 98304 + (size_t)(p * 96) * 256 + s * 64 + ol;
        float a0 = 0.f, a1 = 0.f, a2 = 0.f, a3 = 0.f;
        int ib = p * 96;
        #pragma unroll
        for (int i = 0; i < 96; i += 4) {
            a0 += sin[ib + i + 0] * W[(size_t)(i + 0) * 256];
            a1 += sin[ib + i + 1] * W[(size_t)(i + 1) * 256];
            a2 += sin[ib + i + 2] * W[(size_t)(i + 2) * 256];
            a3 += sin[ib + i + 3] * W[(size_t)(i + 3) * 256];
        }
        sp[tid] = (a0 + a1) + (a2 + a3);
        __syncthreads();
        if (tid < 64) {
            float v = sp[tid] + sp[64 + tid] + sp[128 + tid] + sp[192 + tid]
                    + bl1[n * 256 + s * 64 + tid];
            g_h1[n * 256 + s * 64 + tid] = lrelu(v);
        }
        __threadfence();
        __syncthreads();
        if (tid == 0) atomicAdd(&g_sync[0 * NN + n], 1u);
        spin_wait(&g_sync[0 * NN + n], FS);
        __syncthreads();
    }
    // restore g_d for next replay (all sibling blocks have read it by now)
    if (s == 0)
        for (int i = tid; i < 384; i += 256) g_d[n * 384 + i] = 0.f;

    for (int i = tid; i < 256; i += 256) sin[i] = g_h1[n * 256 + i];
    __syncthreads();

    // ---- L2: 256 -> 256, outputs [s*64, s*64+64) ----
    {
        int ol = tid & 63;
        int p = tid >> 6;                       // 4 parts x 64 inputs
        const float* W = Wl2 + (size_t)n * 65536 + (size_t)(p * 64) * 256 + s * 64 + ol;
        float a0 = 0.f, a1 = 0.f, a2 = 0.f, a3 = 0.f;
        int ib = p * 64;
        #pragma unroll
        for (int i = 0; i < 64; i += 4) {
            a0 += sin[ib + i + 0] * W[(size_t)(i + 0) * 256];
            a1 += sin[ib + i + 1] * W[(size_t)(i + 1) * 256];
            a2 += sin[ib + i + 2] * W[(size_t)(i + 2) * 256];
            a3 += sin[ib + i + 3] * W[(size_t)(i + 3) * 256];
        }
        sp[tid] = (a0 + a1) + (a2 + a3);
        __syncthreads();
        if (tid < 64) {
            float v = sp[tid] + sp[64 + tid] + sp[128 + tid] + sp[192 + tid]
                    + bl2[n * 256 + s * 64 + tid];
            g_h2[n * 256 + s * 64 + tid] = lrelu(v);
        }
        __threadfence();
        __syncthreads();
        if (tid == 0) atomicAdd(&g_sync[1 * NN + n], 1u);
        spin_wait(&g_sync[1 * NN + n], FS);
        __syncthreads();
    }

    for (int i = tid; i < 256; i += 256) sin[i] = g_h2[n * 256 + i];
    __syncthreads();

    // ---- L3: 256 -> 128, outputs [s*32, s*32+32) ----
    {
        int ol = tid & 31;
        int p = tid >> 5;                       // 8 parts x 32 inputs
        const float* W = Wl3 + (size_t)n * 32768 + (size_t)(p * 32) * 128 + s * 32 + ol;
        float a0 = 0.f, a1 = 0.f, a2 = 0.f, a3 = 0.f;
        int ib = p * 32;
        #pragma unroll
        for (int i = 0; i < 32; i += 4) {
            a0 += sin[ib + i + 0] * W[(size_t)(i + 0) * 128];
            a1 += sin[ib + i + 1] * W[(size_t)(i + 1) * 128];
            a2 += sin[ib + i + 2] * W[(size_t)(i + 2) * 128];
            a3 += sin[ib + i + 3] * W[(size_t)(i + 3) * 128];
        }
        sp[tid] = (a0 + a1) + (a2 + a3);
        __syncthreads();
        if (tid < 32) {
            float v = bl3[n * 128 + s * 32 + tid];
            #pragma unroll
            for (int p2 = 0; p2 < 8; p2++) v += sp[p2 * 32 + tid];
            g_h3[n * 128 + s * 32 + tid] = lrelu(v);
        }
        __threadfence();
        __syncthreads();
        if (tid == 0) atomicAdd(&g_sync[2 * NN + n], 1u);
    }

    if (s != 0) return;                          // sibling blocks done

    spin_wait(&g_sync[2 * NN + n], FS);
    __syncthreads();

    if (tid < 128) sin[tid] = g_h3[n * 128 + tid];
    __syncthreads();

    // ---- L4: 128 -> 3 ----
    int warp = tid >> 5, lane = tid & 31;
    if (warp < 3) {
        const float* W = Wl4 + (size_t)n * 384;
        float p = 0.f;
        #pragma unroll
        for (int i = lane; i < 128; i += 32) p += sin[i] * W[i * 3 + warp];
        #pragma unroll
        for (int off = 16; off; off >>= 1) p += __shfl_xor_sync(0xffffffffu, p, off);
        if (lane == 0) g_pre[n * 3 + warp] = p + bl4[n * 3 + warp];
    }

    // -------- fused mean-subtract: last atom-leader block does it --------
    __threadfence();
    __syncthreads();
    __shared__ int s_last;
    if (tid == 0) s_last = (atomicAdd(&g_done, 1) == NN - 1) ? 1 : 0;
    __syncthreads();
    if (s_last) {
        __shared__ float sv[192];
        __shared__ float mean[3];
        if (tid < 192) sv[tid] = __ldcg(&g_pre[tid]);
        __syncthreads();
        if (tid < 3) {
            float msum = 0.f;
            #pragma unroll
            for (int i = 0; i < 64; i++) msum += sv[i * 3 + tid];
            mean[tid] = msum * (1.f / 64.f);
        }
        __syncthreads();
        if (tid < 192) out[tid] = sv[tid] - mean[tid % 3];
        // restore all shared state for the next graph replay; every block is
        // past its spins (g_done==NN implies all leaders finished, which
        // implies every sibling passed its last arrive)
        __syncthreads();
        for (int i = tid; i < 3 * NN; i += 256) g_sync[i] = 0u;
        if (tid == 0) { g_done = 0; g_thead = 0; g_ntiles = 0; g_prep_done = 0u; }
    }
}

// ---------------- launch ----------------
extern "C" void kernel_launch(void* const* d_in, const int* in_sizes, int n_in,
                              void* d_out, int out_size) {
    const float* x   = (const float*)d_in[0];
    const float* We1 = (const float*)d_in[2];
    const float* be1 = (const float*)d_in[3];
    const float* We2 = (const float*)d_in[4];
    const float* be2 = (const float*)d_in[5];
    const float* We3 = (const float*)d_in[6];
    const float* be3 = (const float*)d_in[7];
    const float* Wl1 = (const float*)d_in[8];
    const float* bl1 = (const float*)d_in[9];
    const float* Wl2 = (const float*)d_in[10];
    const float* bl2 = (const float*)d_in[11];
    const float* Wl3 = (const float*)d_in[12];
    const float* bl3 = (const float*)d_in[13];
    const float* Wl4 = (const float*)d_in[14];
    const float* bl4 = (const float*)d_in[15];
    const int*   at  = (const int*)d_in[16];
    float* out = (float*)d_out;

    cudaFuncSetAttribute(k_embed, cudaFuncAttributeMaxDynamicSharedMemorySize,
                         SMEM_FLOATS * (int)sizeof(float));

    k_embed<<<GRID_EMBED, THREADS_E, SMEM_FLOATS * (int)sizeof(float)>>>(
        x, at, We1, be1, We2, be2, We3, be3, Wl1, Wl2, Wl3);
    k_fit<<<NN * FS, 256>>>(Wl1, bl1, Wl2, bl2, Wl3, bl3, Wl4, bl4, out);
}

// round 11
// speedup vs baseline: 1.1305x; 1.1305x over previous
#include <cuda_runtime.h>

#define NN 64
#define MM 1728
#define THREADS_E 256
#define WARPS_PER_BLOCK 8
#define GRID_EMBED 148
#define FS 8          // fit blocks per atom

// ---------------- device scratch (no allocations allowed) ----------------
// Self-cleaning protocol: g_d, g_sync, g_done, g_thead, g_ntiles are zero at
// the start of every kernel_launch call (static zero-init on first call;
// k_fit's final block restores them at the end of each call).
__device__ float g_d[NN * 384];
__device__ float g_h1[NN * 256];
__device__ float g_h2[NN * 256];
__device__ float g_h3[NN * 128];
__device__ float g_pre[NN * 3];
__device__ unsigned g_sync[3 * NN];
__device__ int g_done = 0;
__device__ short g_plist[128][896];   // per-(n,parity) compacted m lists
__device__ int g_tlist[3456];         // flat tile queue entries
__device__ int g_ntiles = 0;
__device__ int g_thead = 0;

__device__ __forceinline__ float lrelu(float v) { return v > 0.f ? v : 0.01f * v; }

// -------- packed f32x2 helpers --------
__device__ __forceinline__ unsigned long long pack2(float v) {
    unsigned long long r;
    asm("mov.b64 %0, {%1, %1};" : "=l"(r) : "r"(__float_as_uint(v)));
    return r;
}
__device__ __forceinline__ void ffma2(unsigned long long& acc, unsigned long long a,
                                      unsigned long long b) {
    asm("fma.rn.f32x2 %0, %1, %2, %0;" : "+l"(acc) : "l"(a), "l"(b));
}
__device__ __forceinline__ void unpack2(unsigned long long v, float& a, float& b) {
    unsigned int lo, hi;
    asm("mov.b64 {%0, %1}, %2;" : "=r"(lo), "=r"(hi) : "l"(v));
    a = __uint_as_float(lo);
    b = __uint_as_float(hi);
}
__device__ __forceinline__ void l2_prefetch(const float* p) {
    asm volatile("prefetch.global.L2 [%0];" :: "l"(p));
}
__device__ __forceinline__ unsigned ld_acq(const unsigned* p) {
    unsigned v;
    asm volatile("ld.acquire.gpu.u32 %0, [%1];" : "=r"(v) : "l"(p) : "memory");
    return v;
}
__device__ __forceinline__ void spin_wait(const unsigned* p, unsigned target) {
    if (ld_acq(p) >= target) return;
    while (ld_acq(p) < target) __nanosleep(64);
}

// ---------------- kernel 0: build compacted kept-pair lists + tile queue ----------
// keep[n][m] = (dist <= 25) && !(c==0 && j==n); list (n,p) holds kept m with
// j parity p (keeps pid warp-uniform downstream). Rank-collapse proof: for c=0
// every pair has dist = |x[j]-x[n]| <= sqrt(300) < 25 (x in [0,10]^3), so the
// first 64 entries of each row are all masked; the (n+1)-th masked entry
// (rank==n) is exactly m = n, the self-pair.
__global__ void k_prep2(const float* __restrict__ x) {
    __shared__ float sx[192];
    int tid = threadIdx.x;
    if (tid < 192) sx[tid] = x[tid];
    __syncthreads();
    int warp = tid >> 5, lane = tid & 31;
    int L = blockIdx.x * 8 + warp;          // 16 blocks x 8 warps = 128 lists
    int n = L >> 1, p = L & 1;
    float xn0 = sx[n * 3 + 0], xn1 = sx[n * 3 + 1], xn2 = sx[n * 3 + 2];
    int cnt = 0;
    for (int tb = 0; tb < 864; tb += 32) {
        int t = tb + lane;
        int c3 = t >> 5, jj = t & 31;
        int j = 2 * jj + p;
        int a = c3 / 9, b = (c3 / 3) % 3, dd = c3 % 3;
        float r0 = sx[j * 3 + 0] + 10.f * a - xn0;
        float r1 = sx[j * 3 + 1] + 10.f * b - xn1;
        float r2 = sx[j * 3 + 2] + 10.f * dd - xn2;
        float d2 = r0 * r0 + r1 * r1 + r2 * r2;
        bool kb = (d2 <= 625.0f) && !(c3 == 0 && j == n);
        unsigned msk = __ballot_sync(0xffffffffu, kb);
        if (kb)
            g_plist[L][cnt + __popc(msk & ((1u << lane) - 1u))] = (short)(c3 * 64 + j);
        cnt += __popc(msk);
    }
    if (lane == 0) {
        int nt = (cnt + 31) >> 5;
        int base = atomicAdd(&g_ntiles, nt);
        for (int i = 0; i < nt; i++) {
            int rem = min(cnt - i * 32, 32);
            g_tlist[base + i] = (L << 10) | (i << 5) | (rem - 1);
        }
    }
}

// ---------------- kernel 1: persistent embedding MLP + contraction ----------------
// smem layout (floats)
#define SW_W1 0
#define SW_B1 288
#define SW_W2 384
#define SW_B2 6528
#define SW_W3 6720
#define SW_B3 31296
#define SW_TOTAL 31680
#define RELK_OFF SW_TOTAL                       // 8 warps * 32 * 4 = 1024
#define SG_OFF (RELK_OFF + 1024)                // 8 warps * 32 * 36 = 9216
#define SMEM_FLOATS (SG_OFF + 9216)             // 41920 floats = 167680 B

__global__ void __launch_bounds__(THREADS_E, 1)
k_embed(const float* __restrict__ x, const int* __restrict__ at,
        const float* __restrict__ We1, const float* __restrict__ be1,
        const float* __restrict__ We2, const float* __restrict__ be2,
        const float* __restrict__ We3, const float* __restrict__ be3,
        const float* __restrict__ Wl1, const float* __restrict__ Wl2,
        const float* __restrict__ Wl3) {
    extern __shared__ float sm[];
    __shared__ float sx[192];
    __shared__ int sat[64];
    int tid = threadIdx.x;
    int warp = tid >> 5, lane = tid & 31;

    // stage all embedding weights into shared once
    {
        const float4* s4;
        float4* d4;
        s4 = (const float4*)We1; d4 = (float4*)(sm + SW_W1);
        for (int i = tid; i < 288 / 4; i += THREADS_E) d4[i] = s4[i];
        s4 = (const float4*)be1; d4 = (float4*)(sm + SW_B1);
        for (int i = tid; i < 96 / 4; i += THREADS_E) d4[i] = s4[i];
        s4 = (const float4*)We2; d4 = (float4*)(sm + SW_W2);
        for (int i = tid; i < 6144 / 4; i += THREADS_E) d4[i] = s4[i];
        s4 = (const float4*)be2; d4 = (float4*)(sm + SW_B2);
        for (int i = tid; i < 192 / 4; i += THREADS_E) d4[i] = s4[i];
        s4 = (const float4*)We3; d4 = (float4*)(sm + SW_W3);
        for (int i = tid; i < 24576 / 4; i += THREADS_E) d4[i] = s4[i];
        s4 = (const float4*)be3; d4 = (float4*)(sm + SW_B3);
        for (int i = tid; i < 384 / 4; i += THREADS_E) d4[i] = s4[i];
    }
    if (tid < 192) sx[tid] = x[tid];
    if (tid < 64) sat[tid] = at[tid];

    // L2-prefetch the fit-net weights (consumed by k_fit); no writeback -> no stalls.
    {
        long long gtid = (long long)blockIdx.x * THREADS_E + tid;
        long long stride = (long long)GRID_EMBED * THREADS_E;
        for (long long o = gtid * 32; o < 6291456LL; o += stride * 32)
            l2_prefetch(Wl1 + o);
        for (long long o = gtid * 32; o < 4194304LL; o += stride * 32)
            l2_prefetch(Wl2 + o);
        for (long long o = gtid * 32; o < 2097152LL; o += stride * 32)
            l2_prefetch(Wl3 + o);
    }
    __syncthreads();

    int ntot = g_ntiles;
    float* relkW = sm + RELK_OFF + warp * 128;   // 32 lanes * float4
    float* sgW = sm + SG_OFF + warp * 1152;      // 32 rows * 36
    float* myrow = sgW + lane * 36;

    for (;;) {
        int idx;
        if (lane == 0) idx = atomicAdd(&g_thead, 1);
        idx = __shfl_sync(0xffffffffu, idx, 0);
        if (idx >= ntot) break;
        int e = g_tlist[idx];
        int L = e >> 10;
        int chunk = (e >> 5) & 31;
        int rem = (e & 31) + 1;
        int n = L >> 1;
        bool valid = lane < rem;
        int m = valid ? (int)g_plist[L][(chunk << 5) + lane] : n;  // dummy: keep=0
        int c3 = m >> 6, j = m & 63;
        int a = c3 / 9, b = (c3 / 3) % 3, dd = c3 % 3;
        // rel = x[j] - x[n] + 10*(a,b,d)
        float r0 = sx[j * 3 + 0] + 10.f * a - sx[n * 3 + 0];
        float r1 = sx[j * 3 + 1] + 10.f * b - sx[n * 3 + 1];
        float r2 = sx[j * 3 + 2] + 10.f * dd - sx[n * 3 + 2];
        float keep = valid ? 1.f : 0.f;

        int tn = sat[n], tj = sat[j];
        int lo = min(tn, tj), hi = max(tn, tj);
        int pid = lo * 2 - (lo * (lo - 1)) / 2 + (hi - lo);

        ((float4*)relkW)[lane] = make_float4(r0 * keep, r1 * keep, r2 * keep, 0.f);

        // ---- layer 1: 3 -> 32 (scalar, tiny) ----
        float h1[32];
        {
            const float* W1 = sm + SW_W1 + pid * 96;
            const float4* B1 = (const float4*)(sm + SW_B1 + pid * 32);
            #pragma unroll
            for (int o4 = 0; o4 < 8; o4++) {
                float4 acc = B1[o4];
                float4 w0 = ((const float4*)(W1 + 0 * 32))[o4];
                float4 w1 = ((const float4*)(W1 + 1 * 32))[o4];
                float4 w2 = ((const float4*)(W1 + 2 * 32))[o4];
                acc.x += r0 * w0.x + r1 * w1.x + r2 * w2.x;
                acc.y += r0 * w0.y + r1 * w1.y + r2 * w2.y;
                acc.z += r0 * w0.z + r1 * w1.z + r2 * w2.z;
                acc.w += r0 * w0.w + r1 * w1.w + r2 * w2.w;
                h1[o4 * 4 + 0] = lrelu(acc.x);
                h1[o4 * 4 + 1] = lrelu(acc.y);
                h1[o4 * 4 + 2] = lrelu(acc.z);
                h1[o4 * 4 + 3] = lrelu(acc.w);
            }
        }

        // ---- layer 2: 32 -> 64, packed f32x2 ----
        float h2[64];
        {
            unsigned long long acc2[32];
            const ulonglong2* B2v = (const ulonglong2*)(sm + SW_B2 + pid * 64);
            #pragma unroll
            for (int o4 = 0; o4 < 16; o4++) {
                ulonglong2 bb = B2v[o4];
                acc2[2 * o4] = bb.x;
                acc2[2 * o4 + 1] = bb.y;
            }
            const ulonglong2* W2v = (const ulonglong2*)(sm + SW_W2 + pid * 2048);
            #pragma unroll
            for (int i = 0; i < 32; i++) {
                unsigned long long hp = pack2(h1[i]);
                const ulonglong2* wrow = W2v + i * 16;
                #pragma unroll
                for (int o4 = 0; o4 < 16; o4++) {
                    ulonglong2 w = wrow[o4];
                    ffma2(acc2[2 * o4], hp, w.x);
                    ffma2(acc2[2 * o4 + 1], hp, w.y);
                }
            }
            #pragma unroll
            for (int p = 0; p < 32; p++) {
                float va, vb;
                unpack2(acc2[p], va, vb);
                h2[2 * p] = lrelu(va);
                h2[2 * p + 1] = lrelu(vb);
            }
        }

        // ---- layer 3: 64 -> 128 in 4 chunks of 32, packed, fused contraction ----
        const ulonglong2* W3v = (const ulonglong2*)(sm + SW_W3 + pid * 8192);
        const ulonglong2* B3v = (const ulonglong2*)(sm + SW_B3 + pid * 128);
        #pragma unroll 1
        for (int k = 0; k < 4; k++) {
            unsigned long long acc3[16];
            #pragma unroll
            for (int o4 = 0; o4 < 8; o4++) {
                ulonglong2 bb = B3v[k * 8 + o4];
                acc3[2 * o4] = bb.x;
                acc3[2 * o4 + 1] = bb.y;
            }
            #pragma unroll
            for (int i = 0; i < 64; i++) {
                unsigned long long hp = pack2(h2[i]);
                const ulonglong2* wrow = W3v + i * 32 + k * 8;
                #pragma unroll
                for (int o4 = 0; o4 < 8; o4++) {
                    ulonglong2 w = wrow[o4];
                    ffma2(acc3[2 * o4], hp, w.x);
                    ffma2(acc3[2 * o4 + 1], hp, w.y);
                }
            }
            #pragma unroll
            for (int o4 = 0; o4 < 8; o4++) {
                float a0, a1, a2, a3;
                unpack2(acc3[2 * o4], a0, a1);
                unpack2(acc3[2 * o4 + 1], a2, a3);
                ((float4*)myrow)[o4] =
                    make_float4(lrelu(a0), lrelu(a1), lrelu(a2), lrelu(a3));
            }
            __syncwarp();
            // warp-local transpose reduce: lane owns output o = k*32 + lane
            float d0 = 0.f, d1 = 0.f, d2s = 0.f;
            #pragma unroll 8
            for (int q = 0; q < 32; q++) {
                float gv = sgW[q * 36 + lane];
                float4 rk = ((const float4*)relkW)[q];
                d0 += gv * rk.x;
                d1 += gv * rk.y;
                d2s += gv * rk.z;
            }
            __syncwarp();
            int o = k * 32 + lane;
            atomicAdd(&g_d[n * 384 + o * 3 + 0], d0);
            atomicAdd(&g_d[n * 384 + o * 3 + 1], d1);
            atomicAdd(&g_d[n * 384 + o * 3 + 2], d2s);
        }
        __syncwarp();
    }
}

// ---------------- kernel 2: multi-block per-atom fit network ----------------
// 8 blocks per atom; per-layer cross-block sync via release/acquire counters.
// All 512 blocks are co-resident (launch_bounds(256,4): 4 blocks/SM * 148 SM
// = 592 slots >= 512) -> spins are deadlock-free.
__global__ void __launch_bounds__(256, 4)
k_fit(const float* __restrict__ Wl1, const float* __restrict__ bl1,
      const float* __restrict__ Wl2, const float* __restrict__ bl2,
      const float* __restrict__ Wl3, const float* __restrict__ bl3,
      const float* __restrict__ Wl4, const float* __restrict__ bl4,
      float* __restrict__ out) {
    __shared__ float sin[384];
    __shared__ float sp[256];
    int blk = blockIdx.x;
    int n = blk >> 3, s = blk & 7;
    int tid = threadIdx.x;

    for (int i = tid; i < 384; i += 256) sin[i] = g_d[n * 384 + i];
    __syncthreads();

    // ---- L1: 384 -> 256, this block owns outputs [s*32, s*32+32) ----
    {
        int ol = tid & 31;
        int p = tid >> 5;                       // 8 parts x 48 inputs
        const float* W = Wl1 + (size_t)n * 98304 + (size_t)(p * 48) * 256 + s * 32 + ol;
        float a0 = 0.f, a1 = 0.f;
        int ib = p * 48;
        #pragma unroll
        for (int i = 0; i < 48; i += 2) {
            a0 += sin[ib + i + 0] * W[(size_t)(i + 0) * 256];
            a1 += sin[ib + i + 1] * W[(size_t)(i + 1) * 256];
        }
        sp[tid] = a0 + a1;
        __syncthreads();
        if (tid < 32) {
            float v = bl1[n * 256 + s * 32 + tid];
            #pragma unroll
            for (int p2 = 0; p2 < 8; p2++) v += sp[p2 * 32 + tid];
            g_h1[n * 256 + s * 32 + tid] = lrelu(v);
        }
        __threadfence();
        __syncthreads();
        if (tid == 0) atomicAdd(&g_sync[0 * NN + n], 1u);
        spin_wait(&g_sync[0 * NN + n], FS);
        __syncthreads();
    }
    // restore g_d for next replay (all sibling blocks have read it by now)
    if (s == 0)
        for (int i = tid; i < 384; i += 256) g_d[n * 384 + i] = 0.f;

    for (int i = tid; i < 256; i += 256) sin[i] = g_h1[n * 256 + i];
    __syncthreads();

    // ---- L2: 256 -> 256, outputs [s*32, s*32+32) ----
    {
        int ol = tid & 31;
        int p = tid >> 5;                       // 8 parts x 32 inputs
        const float* W = Wl2 + (size_t)n * 65536 + (size_t)(p * 32) * 256 + s * 32 + ol;
        float a0 = 0.f, a1 = 0.f;
        int ib = p * 32;
        #pragma unroll
        for (int i = 0; i < 32; i += 2) {
            a0 += sin[ib + i + 0] * W[(size_t)(i + 0) * 256];
            a1 += sin[ib + i + 1] * W[(size_t)(i + 1) * 256];
        }
        sp[tid] = a0 + a1;
        __syncthreads();
        if (tid < 32) {
            float v = bl2[n * 256 + s * 32 + tid];
            #pragma unroll
            for (int p2 = 0; p2 < 8; p2++) v += sp[p2 * 32 + tid];
            g_h2[n * 256 + s * 32 + tid] = lrelu(v);
        }
        __threadfence();
        __syncthreads();
        if (tid == 0) atomicAdd(&g_sync[1 * NN + n], 1u);
        spin_wait(&g_sync[1 * NN + n], FS);
        __syncthreads();
    }

    for (int i = tid; i < 256; i += 256) sin[i] = g_h2[n * 256 + i];
    __syncthreads();

    // ---- L3: 256 -> 128, outputs [s*16, s*16+16) ----
    {
        int ol = tid & 15;
        int p = tid >> 4;                       // 16 parts x 16 inputs
        const float* W = Wl3 + (size_t)n * 32768 + (size_t)(p * 16) * 128 + s * 16 + ol;
        float a0 = 0.f, a1 = 0.f;
        int ib = p * 16;
        #pragma unroll
        for (int i = 0; i < 16; i += 2) {
            a0 += sin[ib + i + 0] * W[(size_t)(i + 0) * 128];
            a1 += sin[ib + i + 1] * W[(size_t)(i + 1) * 128];
        }
        sp[tid] = a0 + a1;
        __syncthreads();
        if (tid < 16) {
            float v = bl3[n * 128 + s * 16 + tid];
            #pragma unroll
            for (int p2 = 0; p2 < 16; p2++) v += sp[p2 * 16 + tid];
            g_h3[n * 128 + s * 16 + tid] = lrelu(v);
        }
        __threadfence();
        __syncthreads();
        if (tid == 0) atomicAdd(&g_sync[2 * NN + n], 1u);
    }

    if (s != 0) return;                          // sibling blocks done

    spin_wait(&g_sync[2 * NN + n], FS);
    __syncthreads();

    if (tid < 128) sin[tid] = g_h3[n * 128 + tid];
    __syncthreads();

    // ---- L4: 128 -> 3 ----
    int warp = tid >> 5, lane = tid & 31;
    if (warp < 3) {
        const float* W = Wl4 + (size_t)n * 384;
        float p = 0.f;
        #pragma unroll
        for (int i = lane; i < 128; i += 32) p += sin[i] * W[i * 3 + warp];
        #pragma unroll
        for (int off = 16; off; off >>= 1) p += __shfl_xor_sync(0xffffffffu, p, off);
        if (lane == 0) g_pre[n * 3 + warp] = p + bl4[n * 3 + warp];
    }

    // -------- fused mean-subtract: last atom-leader block does it --------
    __threadfence();
    __syncthreads();
    __shared__ int s_last;
    if (tid == 0) s_last = (atomicAdd(&g_done, 1) == NN - 1) ? 1 : 0;
    __syncthreads();
    if (s_last) {
        __shared__ float sv[192];
        __shared__ float mean[3];
        if (tid < 192) sv[tid] = __ldcg(&g_pre[tid]);
        __syncthreads();
        if (tid < 3) {
            float msum = 0.f;
            #pragma unroll
            for (int i = 0; i < 64; i++) msum += sv[i * 3 + tid];
            mean[tid] = msum * (1.f / 64.f);
        }
        __syncthreads();
        if (tid < 192) out[tid] = sv[tid] - mean[tid % 3];
        // restore all shared state for the next graph replay; every block is
        // past its spins (g_done==NN implies all leaders finished, which
        // implies every sibling passed its last arrive)
        __syncthreads();
        for (int i = tid; i < 3 * NN; i += 256) g_sync[i] = 0u;
        if (tid == 0) { g_done = 0; g_thead = 0; g_ntiles = 0; }
    }
}

// ---------------- launch ----------------
extern "C" void kernel_launch(void* const* d_in, const int* in_sizes, int n_in,
                              void* d_out, int out_size) {
    const float* x   = (const float*)d_in[0];
    const float* We1 = (const float*)d_in[2];
    const float* be1 = (const float*)d_in[3];
    const float* We2 = (const float*)d_in[4];
    const float* be2 = (const float*)d_in[5];
    const float* We3 = (const float*)d_in[6];
    const float* be3 = (const float*)d_in[7];
    const float* Wl1 = (const float*)d_in[8];
    const float* bl1 = (const float*)d_in[9];
    const float* Wl2 = (const float*)d_in[10];
    const float* bl2 = (const float*)d_in[11];
    const float* Wl3 = (const float*)d_in[12];
    const float* bl3 = (const float*)d_in[13];
    const float* Wl4 = (const float*)d_in[14];
    const float* bl4 = (const float*)d_in[15];
    const int*   at  = (const int*)d_in[16];
    float* out = (float*)d_out;

    cudaFuncSetAttribute(k_embed, cudaFuncAttributeMaxDynamicSharedMemorySize,
                         SMEM_FLOATS * (int)sizeof(float));

    k_prep2<<<16, 256>>>(x);
    k_embed<<<GRID_EMBED, THREADS_E, SMEM_FLOATS * (int)sizeof(float)>>>(
        x, at, We1, be1, We2, be2, We3, be3, Wl1, Wl2, Wl3);
    k_fit<<<NN * FS, 256>>>(Wl1, bl1, Wl2, bl2, Wl3, bl3, Wl4, bl4, out);
}

// round 12
// speedup vs baseline: 1.2593x; 1.1140x over previous
#include <cuda_runtime.h>

#define NN 64
#define MM 1728
#define THREADS_E 256
#define WARPS_PER_BLOCK 8
#define GRID_EMBED 148
#define FS 4          // fit blocks per atom

// ---------------- device scratch (no allocations allowed) ----------------
// Self-cleaning protocol: g_d, g_sync, g_done, g_thead, g_ntiles, g_prep_done
// are zero at the start of every kernel_launch call (static zero-init on the
// first call; k_fit's final block restores them at the end of each call).
__device__ float g_d[NN * 384];
__device__ float g_h1[NN * 256];
__device__ float g_h2[NN * 256];
__device__ float g_h3[NN * 128];
__device__ float g_pre[NN * 3];
__device__ unsigned g_sync[3 * NN];
__device__ int g_done = 0;
__device__ short g_plist[128][896];   // per-(n,parity) compacted m lists
__device__ int g_tlist[3456];         // flat tile queue entries
__device__ int g_ntiles = 0;
__device__ int g_thead = 0;
__device__ unsigned g_prep_done = 0;

__device__ __forceinline__ float lrelu(float v) { return v > 0.f ? v : 0.01f * v; }

// -------- packed f32x2 helpers --------
__device__ __forceinline__ unsigned long long pack2(float v) {
    unsigned long long r;
    asm("mov.b64 %0, {%1, %1};" : "=l"(r) : "r"(__float_as_uint(v)));
    return r;
}
__device__ __forceinline__ void ffma2(unsigned long long& acc, unsigned long long a,
                                      unsigned long long b) {
    asm("fma.rn.f32x2 %0, %1, %2, %0;" : "+l"(acc) : "l"(a), "l"(b));
}
__device__ __forceinline__ void unpack2(unsigned long long v, float& a, float& b) {
    unsigned int lo, hi;
    asm("mov.b64 {%0, %1}, %2;" : "=r"(lo), "=r"(hi) : "l"(v));
    a = __uint_as_float(lo);
    b = __uint_as_float(hi);
}
__device__ __forceinline__ void l2_prefetch(const float* p) {
    asm volatile("prefetch.global.L2 [%0];" :: "l"(p));
}
__device__ __forceinline__ unsigned ld_acq(const unsigned* p) {
    unsigned v;
    asm volatile("ld.acquire.gpu.u32 %0, [%1];" : "=r"(v) : "l"(p) : "memory");
    return v;
}
__device__ __forceinline__ void spin_wait(const unsigned* p, unsigned target) {
    if (ld_acq(p) >= target) return;
    while (ld_acq(p) < target) __nanosleep(64);
}

// ---------------- kernel 1: persistent embedding (fused prep + MLP + contraction) --
// keep[n][m] = (dist <= 25) && !(c==0 && j==n); list (n,p) holds kept m with
// j parity p (keeps pid warp-uniform downstream). Rank-collapse proof: for c=0
// every pair has dist = |x[j]-x[n]| <= sqrt(300) < 25 (x in [0,10]^3), so the
// first 64 entries of each row are all masked; the (n+1)-th masked entry
// (rank==n) is exactly m = n, the self-pair.
//
// smem layout (floats)
#define SW_W1 0
#define SW_B1 288
#define SW_W2 384
#define SW_B2 6528
#define SW_W3 6720
#define SW_B3 31296
#define SW_TOTAL 31680
#define RELK_OFF SW_TOTAL                       // 8 warps * 32 * 4 = 1024
#define SG_OFF (RELK_OFF + 1024)                // 8 warps * 32 * 36 = 9216
#define SMEM_FLOATS (SG_OFF + 9216)             // 41920 floats = 167680 B

__global__ void __launch_bounds__(THREADS_E, 1)
k_embed(const float* __restrict__ x, const int* __restrict__ at,
        const float* __restrict__ We1, const float* __restrict__ be1,
        const float* __restrict__ We2, const float* __restrict__ be2,
        const float* __restrict__ We3, const float* __restrict__ be3,
        const float* __restrict__ Wl1, const float* __restrict__ Wl2,
        const float* __restrict__ Wl3) {
    extern __shared__ float sm[];
    __shared__ float sx[192];
    __shared__ int sat[64];
    int tid = threadIdx.x;
    int warp = tid >> 5, lane = tid & 31;

    if (tid < 192) sx[tid] = x[tid];
    if (tid >= 192 && tid < 256) sat[tid - 192] = at[tid - 192];
    __syncthreads();

    // ---- fused prep: blocks 0..127, warp 0 each build one compacted list ----
    if (blockIdx.x < 128 && warp == 0) {
        int L = blockIdx.x;
        int n = L >> 1, p = L & 1;
        float xn0 = sx[n * 3 + 0], xn1 = sx[n * 3 + 1], xn2 = sx[n * 3 + 2];
        int cnt = 0;
        for (int tb = 0; tb < 864; tb += 32) {
            int t = tb + lane;
            int c3 = t >> 5, jj = t & 31;
            int j = 2 * jj + p;
            int a = c3 / 9, b = (c3 / 3) % 3, dd = c3 % 3;
            float r0 = sx[j * 3 + 0] + 10.f * a - xn0;
            float r1 = sx[j * 3 + 1] + 10.f * b - xn1;
            float r2 = sx[j * 3 + 2] + 10.f * dd - xn2;
            float d2 = r0 * r0 + r1 * r1 + r2 * r2;
            bool kb = (d2 <= 625.0f) && !(c3 == 0 && j == n);
            unsigned msk = __ballot_sync(0xffffffffu, kb);
            if (kb)
                g_plist[L][cnt + __popc(msk & ((1u << lane) - 1u))] =
                    (short)(c3 * 64 + j);
            cnt += __popc(msk);
        }
        if (lane == 0) {
            int nt = (cnt + 31) >> 5;
            int base = atomicAdd(&g_ntiles, nt);
            for (int i = 0; i < nt; i++) {
                int rem = min(cnt - i * 32, 32);
                g_tlist[base + i] = (L << 10) | (i << 5) | (rem - 1);
            }
            __threadfence();
            atomicAdd(&g_prep_done, 1u);
        }
    }

    // ---- stage all embedding weights into shared (remaining warps; warp 0 of
    //      non-prep blocks joins too), plus L2 prefetch of fit-net weights ----
    {
        int stid, sstr;
        if (blockIdx.x < 128) { stid = tid - 32; sstr = THREADS_E - 32; }
        else                  { stid = tid;      sstr = THREADS_E; }
        if (stid >= 0) {
            const float4* s4;
            float4* d4;
            s4 = (const float4*)We1; d4 = (float4*)(sm + SW_W1);
            for (int i = stid; i < 288 / 4; i += sstr) d4[i] = s4[i];
            s4 = (const float4*)be1; d4 = (float4*)(sm + SW_B1);
            for (int i = stid; i < 96 / 4; i += sstr) d4[i] = s4[i];
            s4 = (const float4*)We2; d4 = (float4*)(sm + SW_W2);
            for (int i = stid; i < 6144 / 4; i += sstr) d4[i] = s4[i];
            s4 = (const float4*)be2; d4 = (float4*)(sm + SW_B2);
            for (int i = stid; i < 192 / 4; i += sstr) d4[i] = s4[i];
            s4 = (const float4*)We3; d4 = (float4*)(sm + SW_W3);
            for (int i = stid; i < 24576 / 4; i += sstr) d4[i] = s4[i];
            s4 = (const float4*)be3; d4 = (float4*)(sm + SW_B3);
            for (int i = stid; i < 384 / 4; i += sstr) d4[i] = s4[i];

            // L2-prefetch fit-net weights (consumed by k_fit); no writeback.
            long long gtid = (long long)blockIdx.x * THREADS_E + stid;
            long long stride = (long long)GRID_EMBED * sstr;
            for (long long o = gtid * 32; o < 6291456LL; o += stride * 32)
                l2_prefetch(Wl1 + o);
            for (long long o = gtid * 32; o < 4194304LL; o += stride * 32)
                l2_prefetch(Wl2 + o);
            for (long long o = gtid * 32; o < 2097152LL; o += stride * 32)
                l2_prefetch(Wl3 + o);
        }
    }

    // wait for all 128 lists (all 148 blocks co-resident: grid == #SM at
    // 1 block/SM -> spin is deadlock-free)
    spin_wait(&g_prep_done, 128u);
    __syncthreads();
    int ntot = g_ntiles;

    float* relkW = sm + RELK_OFF + warp * 128;   // 32 lanes * float4
    float* sgW = sm + SG_OFF + warp * 1152;      // 32 rows * 36
    float* myrow = sgW + lane * 36;

    for (;;) {
        int idx;
        if (lane == 0) idx = atomicAdd(&g_thead, 1);
        idx = __shfl_sync(0xffffffffu, idx, 0);
        if (idx >= ntot) break;
        int e = g_tlist[idx];
        int L = e >> 10;
        int chunk = (e >> 5) & 31;
        int rem = (e & 31) + 1;
        int n = L >> 1;
        bool valid = lane < rem;
        int m = valid ? (int)g_plist[L][(chunk << 5) + lane] : n;  // dummy: keep=0
        int c3 = m >> 6, j = m & 63;
        int a = c3 / 9, b = (c3 / 3) % 3, dd = c3 % 3;
        // rel = x[j] - x[n] + 10*(a,b,d)
        float r0 = sx[j * 3 + 0] + 10.f * a - sx[n * 3 + 0];
        float r1 = sx[j * 3 + 1] + 10.f * b - sx[n * 3 + 1];
        float r2 = sx[j * 3 + 2] + 10.f * dd - sx[n * 3 + 2];
        float keep = valid ? 1.f : 0.f;

        int tn = sat[n], tj = sat[j];
        int lo = min(tn, tj), hi = max(tn, tj);
        int pid = lo * 2 - (lo * (lo - 1)) / 2 + (hi - lo);

        ((float4*)relkW)[lane] = make_float4(r0 * keep, r1 * keep, r2 * keep, 0.f);

        // ---- layer 1: 3 -> 32 (scalar, tiny) ----
        float h1[32];
        {
            const float* W1 = sm + SW_W1 + pid * 96;
            const float4* B1 = (const float4*)(sm + SW_B1 + pid * 32);
            #pragma unroll
            for (int o4 = 0; o4 < 8; o4++) {
                float4 acc = B1[o4];
                float4 w0 = ((const float4*)(W1 + 0 * 32))[o4];
                float4 w1 = ((const float4*)(W1 + 1 * 32))[o4];
                float4 w2 = ((const float4*)(W1 + 2 * 32))[o4];
                acc.x += r0 * w0.x + r1 * w1.x + r2 * w2.x;
                acc.y += r0 * w0.y + r1 * w1.y + r2 * w2.y;
                acc.z += r0 * w0.z + r1 * w1.z + r2 * w2.z;
                acc.w += r0 * w0.w + r1 * w1.w + r2 * w2.w;
                h1[o4 * 4 + 0] = lrelu(acc.x);
                h1[o4 * 4 + 1] = lrelu(acc.y);
                h1[o4 * 4 + 2] = lrelu(acc.z);
                h1[o4 * 4 + 3] = lrelu(acc.w);
            }
        }

        // ---- layer 2: 32 -> 64, packed f32x2 ----
        float h2[64];
        {
            unsigned long long acc2[32];
            const ulonglong2* B2v = (const ulonglong2*)(sm + SW_B2 + pid * 64);
            #pragma unroll
            for (int o4 = 0; o4 < 16; o4++) {
                ulonglong2 bb = B2v[o4];
                acc2[2 * o4] = bb.x;
                acc2[2 * o4 + 1] = bb.y;
            }
            const ulonglong2* W2v = (const ulonglong2*)(sm + SW_W2 + pid * 2048);
            #pragma unroll
            for (int i = 0; i < 32; i++) {
                unsigned long long hp = pack2(h1[i]);
                const ulonglong2* wrow = W2v + i * 16;
                #pragma unroll
                for (int o4 = 0; o4 < 16; o4++) {
                    ulonglong2 w = wrow[o4];
                    ffma2(acc2[2 * o4], hp, w.x);
                    ffma2(acc2[2 * o4 + 1], hp, w.y);
                }
            }
            #pragma unroll
            for (int p = 0; p < 32; p++) {
                float va, vb;
                unpack2(acc2[p], va, vb);
                h2[2 * p] = lrelu(va);
                h2[2 * p + 1] = lrelu(vb);
            }
        }

        // ---- layer 3: 64 -> 128 in 4 chunks of 32, packed, fused contraction ----
        const ulonglong2* W3v = (const ulonglong2*)(sm + SW_W3 + pid * 8192);
        const ulonglong2* B3v = (const ulonglong2*)(sm + SW_B3 + pid * 128);
        #pragma unroll 1
        for (int k = 0; k < 4; k++) {
            unsigned long long acc3[16];
            #pragma unroll
            for (int o4 = 0; o4 < 8; o4++) {
                ulonglong2 bb = B3v[k * 8 + o4];
                acc3[2 * o4] = bb.x;
                acc3[2 * o4 + 1] = bb.y;
            }
            #pragma unroll
            for (int i = 0; i < 64; i++) {
                unsigned long long hp = pack2(h2[i]);
                const ulonglong2* wrow = W3v + i * 32 + k * 8;
                #pragma unroll
                for (int o4 = 0; o4 < 8; o4++) {
                    ulonglong2 w = wrow[o4];
                    ffma2(acc3[2 * o4], hp, w.x);
                    ffma2(acc3[2 * o4 + 1], hp, w.y);
                }
            }
            #pragma unroll
            for (int o4 = 0; o4 < 8; o4++) {
                float a0, a1, a2, a3;
                unpack2(acc3[2 * o4], a0, a1);
                unpack2(acc3[2 * o4 + 1], a2, a3);
                ((float4*)myrow)[o4] =
                    make_float4(lrelu(a0), lrelu(a1), lrelu(a2), lrelu(a3));
            }
            __syncwarp();
            // warp-local transpose reduce: lane owns output o = k*32 + lane
            float d0 = 0.f, d1 = 0.f, d2s = 0.f;
            #pragma unroll 8
            for (int q = 0; q < 32; q++) {
                float gv = sgW[q * 36 + lane];
                float4 rk = ((const float4*)relkW)[q];
                d0 += gv * rk.x;
                d1 += gv * rk.y;
                d2s += gv * rk.z;
            }
            __syncwarp();
            int o = k * 32 + lane;
            atomicAdd(&g_d[n * 384 + o * 3 + 0], d0);
            atomicAdd(&g_d[n * 384 + o * 3 + 1], d1);
            atomicAdd(&g_d[n * 384 + o * 3 + 2], d2s);
        }
        __syncwarp();
    }
}

// ---------------- kernel 2: multi-block per-atom fit network ----------------
// 4 blocks per atom; per-layer cross-block sync via release/acquire counters.
// All 256 blocks are co-resident (2 blocks/SM guaranteed) -> spins are safe.
__global__ void __launch_bounds__(256, 2)
k_fit(const float* __restrict__ Wl1, const float* __restrict__ bl1,
      const float* __restrict__ Wl2, const float* __restrict__ bl2,
      const float* __restrict__ Wl3, const float* __restrict__ bl3,
      const float* __restrict__ Wl4, const float* __restrict__ bl4,
      float* __restrict__ out) {
    __shared__ float sin[384];
    __shared__ float sp[256];
    int blk = blockIdx.x;
    int n = blk >> 2, s = blk & 3;
    int tid = threadIdx.x;

    for (int i = tid; i < 384; i += 256) sin[i] = g_d[n * 384 + i];
    __syncthreads();

    // ---- L1: 384 -> 256, this block owns outputs [s*64, s*64+64) ----
    {
        int ol = tid & 63;
        int p = tid >> 6;                       // 4 parts x 96 inputs
        const float* W = Wl1 + (size_t)n * 98304 + (size_t)(p * 96) * 256 + s * 64 + ol;
        float a0 = 0.f, a1 = 0.f, a2 = 0.f, a3 = 0.f;
        int ib = p * 96;
        #pragma unroll
        for (int i = 0; i < 96; i += 4) {
            a0 += sin[ib + i + 0] * W[(size_t)(i + 0) * 256];
            a1 += sin[ib + i + 1] * W[(size_t)(i + 1) * 256];
            a2 += sin[ib + i + 2] * W[(size_t)(i + 2) * 256];
            a3 += sin[ib + i + 3] * W[(size_t)(i + 3) * 256];
        }
        sp[tid] = (a0 + a1) + (a2 + a3);
        __syncthreads();
        if (tid < 64) {
            float v = sp[tid] + sp[64 + tid] + sp[128 + tid] + sp[192 + tid]
                    + bl1[n * 256 + s * 64 + tid];
            g_h1[n * 256 + s * 64 + tid] = lrelu(v);
        }
        __threadfence();
        __syncthreads();
        if (tid == 0) atomicAdd(&g_sync[0 * NN + n], 1u);
        spin_wait(&g_sync[0 * NN + n], FS);
        __syncthreads();
    }
    // restore g_d for next replay (all sibling blocks have read it by now)
    if (s == 0)
        for (int i = tid; i < 384; i += 256) g_d[n * 384 + i] = 0.f;

    for (int i = tid; i < 256; i += 256) sin[i] = g_h1[n * 256 + i];
    __syncthreads();

    // ---- L2: 256 -> 256, outputs [s*64, s*64+64) ----
    {
        int ol = tid & 63;
        int p = tid >> 6;                       // 4 parts x 64 inputs
        const float* W = Wl2 + (size_t)n * 65536 + (size_t)(p * 64) * 256 + s * 64 + ol;
        float a0 = 0.f, a1 = 0.f, a2 = 0.f, a3 = 0.f;
        int ib = p * 64;
        #pragma unroll
        for (int i = 0; i < 64; i += 4) {
            a0 += sin[ib + i + 0] * W[(size_t)(i + 0) * 256];
            a1 += sin[ib + i + 1] * W[(size_t)(i + 1) * 256];
            a2 += sin[ib + i + 2] * W[(size_t)(i + 2) * 256];
            a3 += sin[ib + i + 3] * W[(size_t)(i + 3) * 256];
        }
        sp[tid] = (a0 + a1) + (a2 + a3);
        __syncthreads();
        if (tid < 64) {
            float v = sp[tid] + sp[64 + tid] + sp[128 + tid] + sp[192 + tid]
                    + bl2[n * 256 + s * 64 + tid];
            g_h2[n * 256 + s * 64 + tid] = lrelu(v);
        }
        __threadfence();
        __syncthreads();
        if (tid == 0) atomicAdd(&g_sync[1 * NN + n], 1u);
        spin_wait(&g_sync[1 * NN + n], FS);
        __syncthreads();
    }

    for (int i = tid; i < 256; i += 256) sin[i] = g_h2[n * 256 + i];
    __syncthreads();

    // ---- L3: 256 -> 128, outputs [s*32, s*32+32) ----
    {
        int ol = tid & 31;
        int p = tid >> 5;                       // 8 parts x 32 inputs
        const float* W = Wl3 + (size_t)n * 32768 + (size_t)(p * 32) * 128 + s * 32 + ol;
        float a0 = 0.f, a1 = 0.f, a2 = 0.f, a3 = 0.f;
        int ib = p * 32;
        #pragma unroll
        for (int i = 0; i < 32; i += 4) {
            a0 += sin[ib + i + 0] * W[(size_t)(i + 0) * 128];
            a1 += sin[ib + i + 1] * W[(size_t)(i + 1) * 128];
            a2 += sin[ib + i + 2] * W[(size_t)(i + 2) * 128];
            a3 += sin[ib + i + 3] * W[(size_t)(i + 3) * 128];
        }
        sp[tid] = (a0 + a1) + (a2 + a3);
        __syncthreads();
        if (tid < 32) {
            float v = bl3[n * 128 + s * 32 + tid];
            #pragma unroll
            for (int p2 = 0; p2 < 8; p2++) v += sp[p2 * 32 + tid];
            g_h3[n * 128 + s * 32 + tid] = lrelu(v);
        }
        __threadfence();
        __syncthreads();
        if (tid == 0) atomicAdd(&g_sync[2 * NN + n], 1u);
    }

    if (s != 0) return;                          // sibling blocks done

    spin_wait(&g_sync[2 * NN + n], FS);
    __syncthreads();

    if (tid < 128) sin[tid] = g_h3[n * 128 + tid];
    __syncthreads();

    // ---- L4: 128 -> 3 ----
    int warp = tid >> 5, lane = tid & 31;
    if (warp < 3) {
        const float* W = Wl4 + (size_t)n * 384;
        float p = 0.f;
        #pragma unroll
        for (int i = lane; i < 128; i += 32) p += sin[i] * W[i * 3 + warp];
        #pragma unroll
        for (int off = 16; off; off >>= 1) p += __shfl_xor_sync(0xffffffffu, p, off);
        if (lane == 0) g_pre[n * 3 + warp] = p + bl4[n * 3 + warp];
    }

    // -------- fused mean-subtract: last atom-leader block does it --------
    __threadfence();
    __syncthreads();
    __shared__ int s_last;
    if (tid == 0) s_last = (atomicAdd(&g_done, 1) == NN - 1) ? 1 : 0;
    __syncthreads();
    if (s_last) {
        __shared__ float sv[192];
        __shared__ float mean[3];
        if (tid < 192) sv[tid] = __ldcg(&g_pre[tid]);
        __syncthreads();
        if (tid < 3) {
            float msum = 0.f;
            #pragma unroll
            for (int i = 0; i < 64; i++) msum += sv[i * 3 + tid];
            mean[tid] = msum * (1.f / 64.f);
        }
        __syncthreads();
        if (tid < 192) out[tid] = sv[tid] - mean[tid % 3];
        // restore all shared state for the next graph replay; every block is
        // past its spins (g_done==NN implies all leaders finished, which
        // implies every sibling passed its last arrive)
        __syncthreads();
        for (int i = tid; i < 3 * NN; i += 256) g_sync[i] = 0u;
        if (tid == 0) { g_done = 0; g_thead = 0; g_ntiles = 0; g_prep_done = 0u; }
    }
}

// ---------------- launch ----------------
extern "C" void kernel_launch(void* const* d_in, const int* in_sizes, int n_in,
                              void* d_out, int out_size) {
    const float* x   = (const float*)d_in[0];
    const float* We1 = (const float*)d_in[2];
    const float* be1 = (const float*)d_in[3];
    const float* We2 = (const float*)d_in[4];
    const float* be2 = (const float*)d_in[5];
    const float* We3 = (const float*)d_in[6];
    const float* be3 = (const float*)d_in[7];
    const float* Wl1 = (const float*)d_in[8];
    const float* bl1 = (const float*)d_in[9];
    const float* Wl2 = (const float*)d_in[10];
    const float* bl2 = (const float*)d_in[11];
    const float* Wl3 = (const float*)d_in[12];
    const float* bl3 = (const float*)d_in[13];
    const float* Wl4 = (const float*)d_in[14];
    const float* bl4 = (const float*)d_in[15];
    const int*   at  = (const int*)d_in[16];
    float* out = (float*)d_out;

    cudaFuncSetAttribute(k_embed, cudaFuncAttributeMaxDynamicSharedMemorySize,
                         SMEM_FLOATS * (int)sizeof(float));

    k_embed<<<GRID_EMBED, THREADS_E, SMEM_FLOATS * (int)sizeof(float)>>>(
        x, at, We1, be1, We2, be2, We3, be3, Wl1, Wl2, Wl3);
    k_fit<<<NN * FS, 256>>>(Wl1, bl1, Wl2, bl2, Wl3, bl3, Wl4, bl4, out);
}

// round 14
// speedup vs baseline: 1.7987x; 1.4283x over previous
#include <cuda_runtime.h>

#define NN 64
#define MM 1728
#define THREADS_E 256
#define WARPS_PER_BLOCK 8
#define GRID_EMBED 148
#define FS 4          // fit blocks per atom

// ---------------- device scratch (no allocations allowed) ----------------
// Self-cleaning protocol: g_d, g_sync, g_done, g_thead, g_ntiles, g_prep_done
// are zero at the start of every kernel_launch call (static zero-init on the
// first call; k_fit's final block restores them at the end of each call).
__device__ float g_d[NN * 384];
__device__ float g_h1[NN * 256];
__device__ float g_h2[NN * 256];
__device__ float g_h3[NN * 128];
__device__ float g_pre[NN * 3];
__device__ unsigned g_sync[3 * NN];
__device__ int g_done = 0;
__device__ short g_plist[128][896];   // per-(n,parity) compacted m lists
__device__ int g_tlist[1792];         // flat 64-pair tile queue entries
__device__ int g_ntiles = 0;
__device__ int g_thead = 0;
__device__ unsigned g_prep_done = 0;

__device__ __forceinline__ float lrelu(float v) { return v > 0.f ? v : 0.01f * v; }

// -------- packed f32x2 helpers --------
__device__ __forceinline__ unsigned long long pack2(float v) {
    unsigned long long r;
    asm("mov.b64 %0, {%1, %1};" : "=l"(r) : "r"(__float_as_uint(v)));
    return r;
}
__device__ __forceinline__ void ffma2(unsigned long long& acc, unsigned long long a,
                                      unsigned long long b) {
    asm("fma.rn.f32x2 %0, %1, %2, %0;" : "+l"(acc) : "l"(a), "l"(b));
}
__device__ __forceinline__ void unpack2(unsigned long long v, float& a, float& b) {
    unsigned int lo, hi;
    asm("mov.b64 {%0, %1}, %2;" : "=r"(lo), "=r"(hi) : "l"(v));
    a = __uint_as_float(lo);
    b = __uint_as_float(hi);
}
__device__ __forceinline__ void l2_prefetch(const float* p) {
    asm volatile("prefetch.global.L2 [%0];" :: "l"(p));
}
__device__ __forceinline__ unsigned ld_acq(const unsigned* p) {
    unsigned v;
    asm volatile("ld.acquire.gpu.u32 %0, [%1];" : "=r"(v) : "l"(p) : "memory");
    return v;
}
__device__ __forceinline__ void spin_wait(const unsigned* p, unsigned target) {
    if (ld_acq(p) >= target) return;
    while (ld_acq(p) < target) __nanosleep(64);
}

// smem layout (floats)
#define SW_W1 0
#define SW_B1 288
#define SW_W2 384
#define SW_B2 6528
#define SW_W3 6720
#define SW_B3 31296
#define SW_TOTAL 31680
#define RELK_OFF SW_TOTAL                       // 8 warps * 64 * 4 = 2048
#define SGA_OFF (RELK_OFF + 2048)               // 8 warps * 32 * 36 = 9216
#define SGB_OFF (SGA_OFF + 9216)                // 9216
#define SMEM_FLOATS (SGB_OFF + 9216)            // 52160 floats = 208640 B

// ---- layer 2 (32 -> 64), packed f32x2, one pair; fully unrolled ----
__device__ __forceinline__ void layer2(const float* sm, int pid,
                                       const float* h1, float* h2) {
    unsigned long long acc2[32];
    const ulonglong2* B2v = (const ulonglong2*)(sm + SW_B2 + pid * 64);
    #pragma unroll
    for (int o4 = 0; o4 < 16; o4++) {
        ulonglong2 bb = B2v[o4];
        acc2[2 * o4] = bb.x;
        acc2[2 * o4 + 1] = bb.y;
    }
    const ulonglong2* W2v = (const ulonglong2*)(sm + SW_W2 + pid * 2048);
    #pragma unroll
    for (int i = 0; i < 32; i++) {
        unsigned long long hp = pack2(h1[i]);
        const ulonglong2* wrow = W2v + i * 16;
        #pragma unroll
        for (int o4 = 0; o4 < 16; o4++) {
            ulonglong2 w = wrow[o4];
            ffma2(acc2[2 * o4], hp, w.x);
            ffma2(acc2[2 * o4 + 1], hp, w.y);
        }
    }
    #pragma unroll
    for (int p = 0; p < 32; p++) {
        float va, vb;
        unpack2(acc2[p], va, vb);
        h2[2 * p] = lrelu(va);
        h2[2 * p + 1] = lrelu(vb);
    }
}

// ---------------- kernel 1: persistent embedding (fused prep + MLP + contraction) --
// keep[n][m] = (dist <= 25) && !(c==0 && j==n); list (n,p) holds kept m with
// j parity p (pid list-uniform). Rank-collapse proof: for c=0 every pair has
// dist = |x[j]-x[n]| <= sqrt(300) < 25 (x in [0,10]^3), so the first 64
// entries of each row are all masked; the (n+1)-th masked entry (rank==n) is
// exactly m = n, the self-pair.
__global__ void __launch_bounds__(THREADS_E, 1)
k_embed(const float* __restrict__ x, const int* __restrict__ at,
        const float* __restrict__ We1, const float* __restrict__ be1,
        const float* __restrict__ We2, const float* __restrict__ be2,
        const float* __restrict__ We3, const float* __restrict__ be3,
        const float* __restrict__ Wl1, const float* __restrict__ Wl2,
        const float* __restrict__ Wl3) {
    extern __shared__ float sm[];
    __shared__ float sx[192];
    __shared__ int sat[64];
    int tid = threadIdx.x;
    int warp = tid >> 5, lane = tid & 31;

    if (tid < 192) sx[tid] = x[tid];
    if (tid >= 192 && tid < 256) sat[tid - 192] = at[tid - 192];
    __syncthreads();

    // ---- fused prep: blocks 0..127, warp 0 each build one compacted list ----
    if (blockIdx.x < 128 && warp == 0) {
        int L = blockIdx.x;
        int n = L >> 1, p = L & 1;
        float xn0 = sx[n * 3 + 0], xn1 = sx[n * 3 + 1], xn2 = sx[n * 3 + 2];
        int cnt = 0;
        for (int tb = 0; tb < 864; tb += 32) {
            int t = tb + lane;
            int c3 = t >> 5, jj = t & 31;
            int j = 2 * jj + p;
            int a = c3 / 9, b = (c3 / 3) % 3, dd = c3 % 3;
            float r0 = sx[j * 3 + 0] + 10.f * a - xn0;
            float r1 = sx[j * 3 + 1] + 10.f * b - xn1;
            float r2 = sx[j * 3 + 2] + 10.f * dd - xn2;
            float d2 = r0 * r0 + r1 * r1 + r2 * r2;
            bool kb = (d2 <= 625.0f) && !(c3 == 0 && j == n);
            unsigned msk = __ballot_sync(0xffffffffu, kb);
            if (kb)
                g_plist[L][cnt + __popc(msk & ((1u << lane) - 1u))] =
                    (short)(c3 * 64 + j);
            cnt += __popc(msk);
        }
        if (lane == 0) {
            int nt = (cnt + 63) >> 6;                 // 64-pair tiles
            int base = atomicAdd(&g_ntiles, nt);
            for (int i = 0; i < nt; i++) {
                int rem = min(cnt - i * 64, 64);
                g_tlist[base + i] = (L << 11) | (i << 6) | (rem - 1);
            }
            __threadfence();
            atomicAdd(&g_prep_done, 1u);
        }
    }

    // ---- stage all embedding weights into shared (remaining warps; warp 0 of
    //      non-prep blocks joins too), plus L2 prefetch of fit-net weights ----
    {
        int stid, sstr;
        if (blockIdx.x < 128) { stid = tid - 32; sstr = THREADS_E - 32; }
        else                  { stid = tid;      sstr = THREADS_E; }
        if (stid >= 0) {
            const float4* s4;
            float4* d4;
            s4 = (const float4*)We1; d4 = (float4*)(sm + SW_W1);
            for (int i = stid; i < 288 / 4; i += sstr) d4[i] = s4[i];
            s4 = (const float4*)be1; d4 = (float4*)(sm + SW_B1);
            for (int i = stid; i < 96 / 4; i += sstr) d4[i] = s4[i];
            s4 = (const float4*)We2; d4 = (float4*)(sm + SW_W2);
            for (int i = stid; i < 6144 / 4; i += sstr) d4[i] = s4[i];
            s4 = (const float4*)be2; d4 = (float4*)(sm + SW_B2);
            for (int i = stid; i < 192 / 4; i += sstr) d4[i] = s4[i];
            s4 = (const float4*)We3; d4 = (float4*)(sm + SW_W3);
            for (int i = stid; i < 24576 / 4; i += sstr) d4[i] = s4[i];
            s4 = (const float4*)be3; d4 = (float4*)(sm + SW_B3);
            for (int i = stid; i < 384 / 4; i += sstr) d4[i] = s4[i];

            // L2-prefetch fit-net weights (consumed by k_fit); no writeback.
            long long gtid = (long long)blockIdx.x * THREADS_E + stid;
            long long stride = (long long)GRID_EMBED * sstr;
            for (long long o = gtid * 32; o < 6291456LL; o += stride * 32)
                l2_prefetch(Wl1 + o);
            for (long long o = gtid * 32; o < 4194304LL; o += stride * 32)
                l2_prefetch(Wl2 + o);
            for (long long o = gtid * 32; o < 2097152LL; o += stride * 32)
                l2_prefetch(Wl3 + o);
        }
    }

    // wait for all 128 lists (all 148 blocks co-resident: 1 block/SM)
    spin_wait(&g_prep_done, 128u);
    __syncthreads();
    int ntot = g_ntiles;

    float* relkW = sm + RELK_OFF + warp * 256;   // 64 entries * float4
    float* sgWA = sm + SGA_OFF + warp * 1152;    // 32 rows * 36
    float* sgWB = sm + SGB_OFF + warp * 1152;
    float* myrowA = sgWA + lane * 36;
    float* myrowB = sgWB + lane * 36;
    const float4* relk4 = (const float4*)relkW;

    for (;;) {
        int idx;
        if (lane == 0) idx = atomicAdd(&g_thead, 1);
        idx = __shfl_sync(0xffffffffu, idx, 0);
        if (idx >= ntot) break;
        int e = g_tlist[idx];
        int L = e >> 11;
        int chunk = (e >> 6) & 31;
        int rem = (e & 63) + 1;
        int n = L >> 1;
        const short* lst = &g_plist[L][chunk << 6];
        bool vA = lane < rem;
        bool vB = lane + 32 < rem;
        int mA = vA ? (int)lst[lane] : n;          // dummy: keep=0
        int mB = vB ? (int)lst[lane + 32] : n;

        // rel = x[j] - x[n] + 10*(a,b,d)
        int cA = mA >> 6, jA = mA & 63;
        int aA_ = cA / 9, bA_ = (cA / 3) % 3, dA_ = cA % 3;
        float rA0 = sx[jA * 3 + 0] + 10.f * aA_ - sx[n * 3 + 0];
        float rA1 = sx[jA * 3 + 1] + 10.f * bA_ - sx[n * 3 + 1];
        float rA2 = sx[jA * 3 + 2] + 10.f * dA_ - sx[n * 3 + 2];
        int cB = mB >> 6, jB = mB & 63;
        int aB_ = cB / 9, bB_ = (cB / 3) % 3, dB_ = cB % 3;
        float rB0 = sx[jB * 3 + 0] + 10.f * aB_ - sx[n * 3 + 0];
        float rB1 = sx[jB * 3 + 1] + 10.f * bB_ - sx[n * 3 + 1];
        float rB2 = sx[jB * 3 + 2] + 10.f * dB_ - sx[n * 3 + 2];
        float kA = vA ? 1.f : 0.f;
        float kB = vB ? 1.f : 0.f;

        // pid: uniform across the list; take it from lane 0's (always valid) pair
        int mRef = __shfl_sync(0xffffffffu, mA, 0);
        int tn = sat[n], tj = sat[mRef & 63];
        int lo = min(tn, tj), hi = max(tn, tj);
        int pid = lo * 2 - (lo * (lo - 1)) / 2 + (hi - lo);

        ((float4*)relkW)[lane] = make_float4(rA0 * kA, rA1 * kA, rA2 * kA, 0.f);
        ((float4*)relkW)[32 + lane] = make_float4(rB0 * kB, rB1 * kB, rB2 * kB, 0.f);

        // ---- layer 1: 3 -> 32 for both pairs, shared weight loads ----
        float h1A[32], h1B[32];
        {
            const float* W1 = sm + SW_W1 + pid * 96;
            const float4* B1 = (const float4*)(sm + SW_B1 + pid * 32);
            #pragma unroll
            for (int o4 = 0; o4 < 8; o4++) {
                float4 bb = B1[o4];
                float4 w0 = ((const float4*)(W1 + 0 * 32))[o4];
                float4 w1 = ((const float4*)(W1 + 1 * 32))[o4];
                float4 w2 = ((const float4*)(W1 + 2 * 32))[o4];
                h1A[o4 * 4 + 0] = lrelu(bb.x + rA0 * w0.x + rA1 * w1.x + rA2 * w2.x);
                h1A[o4 * 4 + 1] = lrelu(bb.y + rA0 * w0.y + rA1 * w1.y + rA2 * w2.y);
                h1A[o4 * 4 + 2] = lrelu(bb.z + rA0 * w0.z + rA1 * w1.z + rA2 * w2.z);
                h1A[o4 * 4 + 3] = lrelu(bb.w + rA0 * w0.w + rA1 * w1.w + rA2 * w2.w);
                h1B[o4 * 4 + 0] = lrelu(bb.x + rB0 * w0.x + rB1 * w1.x + rB2 * w2.x);
                h1B[o4 * 4 + 1] = lrelu(bb.y + rB0 * w0.y + rB1 * w1.y + rB2 * w2.y);
                h1B[o4 * 4 + 2] = lrelu(bb.z + rB0 * w0.z + rB1 * w1.z + rB2 * w2.z);
                h1B[o4 * 4 + 3] = lrelu(bb.w + rB0 * w0.w + rB1 * w1.w + rB2 * w2.w);
            }
        }

        // ---- layer 2: 32 -> 64, per pair (keeps register peak low) ----
        float h2A[64], h2B[64];
        layer2(sm, pid, h1A, h2A);
        layer2(sm, pid, h1B, h2B);

        // ---- layer 3: 64 -> 128 in 4 chunks of 32 (2 halves of 16 each),
        //      shared weight loads feed both pairs; fused contraction ----
        const ulonglong2* W3v = (const ulonglong2*)(sm + SW_W3 + pid * 8192);
        const ulonglong2* B3v = (const ulonglong2*)(sm + SW_B3 + pid * 128);
        #pragma unroll 1
        for (int k = 0; k < 4; k++) {
            #pragma unroll 1
            for (int h = 0; h < 2; h++) {
                unsigned long long aA[8], aB[8];
                const ulonglong2* bb4 = B3v + k * 8 + h * 4;
                #pragma unroll
                for (int o4 = 0; o4 < 4; o4++) {
                    ulonglong2 b2 = bb4[o4];
                    aA[2 * o4] = b2.x; aA[2 * o4 + 1] = b2.y;
                    aB[2 * o4] = b2.x; aB[2 * o4 + 1] = b2.y;
                }
                const ulonglong2* wbase = W3v + k * 8 + h * 4;
                #pragma unroll
                for (int i = 0; i < 64; i++) {
                    unsigned long long hA = pack2(h2A[i]);
                    unsigned long long hB = pack2(h2B[i]);
                    const ulonglong2* wrow = wbase + i * 32;
                    #pragma unroll
                    for (int o4 = 0; o4 < 4; o4++) {
                        ulonglong2 w = wrow[o4];
                        ffma2(aA[2 * o4], hA, w.x);
                        ffma2(aA[2 * o4 + 1], hA, w.y);
                        ffma2(aB[2 * o4], hB, w.x);
                        ffma2(aB[2 * o4 + 1], hB, w.y);
                    }
                }
                #pragma unroll
                for (int o4 = 0; o4 < 4; o4++) {
                    float a0, a1, a2, a3;
                    unpack2(aA[2 * o4], a0, a1);
                    unpack2(aA[2 * o4 + 1], a2, a3);
                    ((float4*)myrowA)[h * 4 + o4] =
                        make_float4(lrelu(a0), lrelu(a1), lrelu(a2), lrelu(a3));
                    unpack2(aB[2 * o4], a0, a1);
                    unpack2(aB[2 * o4 + 1], a2, a3);
                    ((float4*)myrowB)[h * 4 + o4] =
                        make_float4(lrelu(a0), lrelu(a1), lrelu(a2), lrelu(a3));
                }
            }
            __syncwarp();
            // warp-local transpose reduce: lane owns output o = k*32 + lane
            float d0 = 0.f, d1 = 0.f, d2s = 0.f;
            #pragma unroll 8
            for (int q = 0; q < 32; q++) {
                float gA = sgWA[q * 36 + lane];
                float4 rA = relk4[q];
                d0 += gA * rA.x; d1 += gA * rA.y; d2s += gA * rA.z;
                float gB = sgWB[q * 36 + lane];
                float4 rB = relk4[32 + q];
                d0 += gB * rB.x; d1 += gB * rB.y; d2s += gB * rB.z;
            }
            __syncwarp();
            int o = k * 32 + lane;
            atomicAdd(&g_d[n * 384 + o * 3 + 0], d0);
            atomicAdd(&g_d[n * 384 + o * 3 + 1], d1);
            atomicAdd(&g_d[n * 384 + o * 3 + 2], d2s);
        }
        __syncwarp();
    }
}

// ---------------- kernel 2: multi-block per-atom fit network ----------------
// 4 blocks per atom; per-layer cross-block sync via release/acquire counters.
// All 256 blocks are co-resident (2 blocks/SM guaranteed) -> spins are safe.
__global__ void __launch_bounds__(256, 2)
k_fit(const float* __restrict__ Wl1, const float* __restrict__ bl1,
      const float* __restrict__ Wl2, const float* __restrict__ bl2,
      const float* __restrict__ Wl3, const float* __restrict__ bl3,
      const float* __restrict__ Wl4, const float* __restrict__ bl4,
      float* __restrict__ out) {
    __shared__ float sin[384];
    __shared__ float sp[256];
    int blk = blockIdx.x;
    int n = blk >> 2, s = blk & 3;
    int tid = threadIdx.x;

    for (int i = tid; i < 384; i += 256) sin[i] = g_d[n * 384 + i];
    __syncthreads();

    // ---- L1: 384 -> 256, this block owns outputs [s*64, s*64+64) ----
    {
        int ol = tid & 63;
        int p = tid >> 6;                       // 4 parts x 96 inputs
        const float* W = Wl1 + (size_t)n * 98304 + (size_t)(p * 96) * 256 + s * 64 + ol;
        float a0 = 0.f, a1 = 0.f, a2 = 0.f, a3 = 0.f;
        int ib = p * 96;
        #pragma unroll
        for (int i = 0; i < 96; i += 4) {
            a0 += sin[ib + i + 0] * W[(size_t)(i + 0) * 256];
            a1 += sin[ib + i + 1] * W[(size_t)(i + 1) * 256];
            a2 += sin[ib + i + 2] * W[(size_t)(i + 2) * 256];
            a3 += sin[ib + i + 3] * W[(size_t)(i + 3) * 256];
        }
        sp[tid] = (a0 + a1) + (a2 + a3);
        __syncthreads();
        if (tid < 64) {
            float v = sp[tid] + sp[64 + tid] + sp[128 + tid] + sp[192 + tid]
                    + bl1[n * 256 + s * 64 + tid];
            g_h1[n * 256 + s * 64 + tid] = lrelu(v);
        }
        __threadfence();
        __syncthreads();
        if (tid == 0) atomicAdd(&g_sync[0 * NN + n], 1u);
        spin_wait(&g_sync[0 * NN + n], FS);
        __syncthreads();
    }
    // restore g_d for next replay (all sibling blocks have read it by now)
    if (s == 0)
        for (int i = tid; i < 384; i += 256) g_d[n * 384 + i] = 0.f;

    for (int i = tid; i < 256; i += 256) sin[i] = g_h1[n * 256 + i];
    __syncthreads();

    // ---- L2: 256 -> 256, outputs [s*64, s*64+64) ----
    {
        int ol = tid & 63;
        int p = tid >> 6;                       // 4 parts x 64 inputs
        const float* W = Wl2 + (size_t)n * 65536 + (size_t)(p * 64) * 256 + s * 64 + ol;
        float a0 = 0.f, a1 = 0.f, a2 = 0.f, a3 = 0.f;
        int ib = p * 64;
        #pragma unroll
        for (int i = 0; i < 64; i += 4) {
            a0 += sin[ib + i + 0] * W[(size_t)(i + 0) * 256];
            a1 += sin[ib + i + 1] * W[(size_t)(i + 1) * 256];
            a2 += sin[ib + i + 2] * W[(size_t)(i + 2) * 256];
            a3 += sin[ib + i + 3] * W[(size_t)(i + 3) * 256];
        }
        sp[tid] = (a0 + a1) + (a2 + a3);
        __syncthreads();
        if (tid < 64) {
            float v = sp[tid] + sp[64 + tid] + sp[128 + tid] + sp[192 + tid]
                    + bl2[n * 256 + s * 64 + tid];
            g_h2[n * 256 + s * 64 + tid] = lrelu(v);
        }
        __threadfence();
        __syncthreads();
        if (tid == 0) atomicAdd(&g_sync[1 * NN + n], 1u);
        spin_wait(&g_sync[1 * NN + n], FS);
        __syncthreads();
    }

    for (int i = tid; i < 256; i += 256) sin[i] = g_h2[n * 256 + i];
    __syncthreads();

    // ---- L3: 256 -> 128, outputs [s*32, s*32+32) ----
    {
        int ol = tid & 31;
        int p = tid >> 5;                       // 8 parts x 32 inputs
        const float* W = Wl3 + (size_t)n * 32768 + (size_t)(p * 32) * 128 + s * 32 + ol;
        float a0 = 0.f, a1 = 0.f, a2 = 0.f, a3 = 0.f;
        int ib = p * 32;
        #pragma unroll
        for (int i = 0; i < 32; i += 4) {
            a0 += sin[ib + i + 0] * W[(size_t)(i + 0) * 128];
            a1 += sin[ib + i + 1] * W[(size_t)(i + 1) * 128];
            a2 += sin[ib + i + 2] * W[(size_t)(i + 2) * 128];
            a3 += sin[ib + i + 3] * W[(size_t)(i + 3) * 128];
        }
        sp[tid] = (a0 + a1) + (a2 + a3);
        __syncthreads();
        if (tid < 32) {
            float v = bl3[n * 128 + s * 32 + tid];
            #pragma unroll
            for (int p2 = 0; p2 < 8; p2++) v += sp[p2 * 32 + tid];
            g_h3[n * 128 + s * 32 + tid] = lrelu(v);
        }
        __threadfence();
        __syncthreads();
        if (tid == 0) atomicAdd(&g_sync[2 * NN + n], 1u);
    }

    if (s != 0) return;                          // sibling blocks done

    spin_wait(&g_sync[2 * NN + n], FS);
    __syncthreads();

    if (tid < 128) sin[tid] = g_h3[n * 128 + tid];
    __syncthreads();

    // ---- L4: 128 -> 3 ----
    int warp = tid >> 5, lane = tid & 31;
    if (warp < 3) {
        const float* W = Wl4 + (size_t)n * 384;
        float p = 0.f;
        #pragma unroll
        for (int i = lane; i < 128; i += 32) p += sin[i] * W[i * 3 + warp];
        #pragma unroll
        for (int off = 16; off; off >>= 1) p += __shfl_xor_sync(0xffffffffu, p, off);
        if (lane == 0) g_pre[n * 3 + warp] = p + bl4[n * 3 + warp];
    }

    // -------- fused mean-subtract: last atom-leader block does it --------
    __threadfence();
    __syncthreads();
    __shared__ int s_last;
    if (tid == 0) s_last = (atomicAdd(&g_done, 1) == NN - 1) ? 1 : 0;
    __syncthreads();
    if (s_last) {
        __shared__ float sv[192];
        __shared__ float mean[3];
        if (tid < 192) sv[tid] = __ldcg(&g_pre[tid]);
        __syncthreads();
        if (tid < 3) {
            float msum = 0.f;
            #pragma unroll
            for (int i = 0; i < 64; i++) msum += sv[i * 3 + tid];
            mean[tid] = msum * (1.f / 64.f);
        }
        __syncthreads();
        if (tid < 192) out[tid] = sv[tid] - mean[tid % 3];
        // restore all shared state for the next graph replay; every block is
        // past its spins (g_done==NN implies all leaders finished, which
        // implies every sibling passed its last arrive)
        __syncthreads();
        for (int i = tid; i < 3 * NN; i += 256) g_sync[i] = 0u;
        if (tid == 0) { g_done = 0; g_thead = 0; g_ntiles = 0; g_prep_done = 0u; }
    }
}

// ---------------- launch ----------------
extern "C" void kernel_launch(void* const* d_in, const int* in_sizes, int n_in,
                              void* d_out, int out_size) {
    const float* x   = (const float*)d_in[0];
    const float* We1 = (const float*)d_in[2];
    const float* be1 = (const float*)d_in[3];
    const float* We2 = (const float*)d_in[4];
    const float* be2 = (const float*)d_in[5];
    const float* We3 = (const float*)d_in[6];
    const float* be3 = (const float*)d_in[7];
    const float* Wl1 = (const float*)d_in[8];
    const float* bl1 = (const float*)d_in[9];
    const float* Wl2 = (const float*)d_in[10];
    const float* bl2 = (const float*)d_in[11];
    const float* Wl3 = (const float*)d_in[12];
    const float* bl3 = (const float*)d_in[13];
    const float* Wl4 = (const float*)d_in[14];
    const float* bl4 = (const float*)d_in[15];
    const int*   at  = (const int*)d_in[16];
    float* out = (float*)d_out;

    cudaFuncSetAttribute(k_embed, cudaFuncAttributeMaxDynamicSharedMemorySize,
                         SMEM_FLOATS * (int)sizeof(float));

    k_embed<<<GRID_EMBED, THREADS_E, SMEM_FLOATS * (int)sizeof(float)>>>(
        x, at, We1, be1, We2, be2, We3, be3, Wl1, Wl2, Wl3);
    k_fit<<<NN * FS, 256>>>(Wl1, bl1, Wl2, bl2, Wl3, bl3, Wl4, bl4, out);
}